// round 1
// baseline (speedup 1.0000x reference)
#include <cuda_runtime.h>
#include <cuda_bf16.h>
#include <cstdint>

#define N_NODES 100000
#define N_EDGES 1600000
#define D_IN    32
#define D_OUT   64

#define SCAN_BLK   1024
#define N_SCAN_BLK ((N_NODES + SCAN_BLK - 1) / SCAN_BLK)   // 98

// ---------------- scratch (static __device__ allocations only) ----------------
__device__ float g_xbuf0[N_NODES * D_IN];
__device__ float g_xbuf1[N_NODES * D_IN];
__device__ int   g_cnt [N_NODES];
__device__ int   g_excl[N_NODES];
__device__ int   g_bsum[128];
__device__ int   g_boff[128];
__device__ int   g_rowstart[N_NODES + 1];
__device__ int   g_pos[N_NODES];
__device__ int2  g_csr[N_EDGES];          // {col, val bits}

// ---------------- CSR build ----------------
__global__ void k_hist(const int* __restrict__ row) {
    int e = blockIdx.x * blockDim.x + threadIdx.x;
    if (e < N_EDGES) atomicAdd(&g_cnt[row[e]], 1);
}

__global__ void k_scan_block() {
    __shared__ int s[SCAN_BLK];
    int tid = threadIdx.x;
    int i   = blockIdx.x * SCAN_BLK + tid;
    int v   = (i < N_NODES) ? g_cnt[i] : 0;
    s[tid] = v;
    __syncthreads();
    #pragma unroll
    for (int off = 1; off < SCAN_BLK; off <<= 1) {
        int t = (tid >= off) ? s[tid - off] : 0;
        __syncthreads();
        s[tid] += t;
        __syncthreads();
    }
    int incl = s[tid];
    if (i < N_NODES) g_excl[i] = incl - v;
    if (tid == SCAN_BLK - 1) g_bsum[blockIdx.x] = incl;
}

__global__ void k_scan_sums() {
    __shared__ int s[128];
    int tid = threadIdx.x;   // 128 threads
    int v = (tid < N_SCAN_BLK) ? g_bsum[tid] : 0;
    s[tid] = v;
    __syncthreads();
    #pragma unroll
    for (int off = 1; off < 128; off <<= 1) {
        int t = (tid >= off) ? s[tid - off] : 0;
        __syncthreads();
        s[tid] += t;
        __syncthreads();
    }
    if (tid < N_SCAN_BLK) g_boff[tid] = s[tid] - v;
}

__global__ void k_scan_add() {
    int i = blockIdx.x * SCAN_BLK + threadIdx.x;
    if (i < N_NODES) g_rowstart[i] = g_excl[i] + g_boff[blockIdx.x];
    if (blockIdx.x == 0 && threadIdx.x == 0) g_rowstart[N_NODES] = N_EDGES;
}

__global__ void k_scatter(const int* __restrict__ row,
                          const int* __restrict__ col,
                          const float* __restrict__ val) {
    int e = blockIdx.x * blockDim.x + threadIdx.x;
    if (e < N_EDGES) {
        int r = row[e];
        int p = atomicAdd(&g_pos[r], 1);
        g_csr[p] = make_int2(col[e], __float_as_int(val[e]));
    }
}

// ---------------- SpMM: one warp per node, lane = feature dim ----------------
// FUSE: apply the final dense linear (x @ W + b) in-register and write D_OUT.
template <bool FUSE>
__global__ void k_spmm(const float* __restrict__ xin,
                       float* __restrict__ xout,
                       const float* __restrict__ W,
                       const float* __restrict__ b) {
    __shared__ float Ws[D_IN * D_OUT];   // 8 KB
    __shared__ float bs[D_OUT];
    if (FUSE) {
        for (int i = threadIdx.x; i < D_IN * D_OUT; i += blockDim.x) Ws[i] = W[i];
        if (threadIdx.x < D_OUT) bs[threadIdx.x] = b[threadIdx.x];
        __syncthreads();
    }

    int gwarp = (blockIdx.x * blockDim.x + threadIdx.x) >> 5;
    int lane  = threadIdx.x & 31;
    if (gwarp >= N_NODES) return;

    int start = g_rowstart[gwarp];
    int end   = g_rowstart[gwarp + 1];

    float acc = 0.f;
    int e = start;
    // unroll by 2 to expose MLP on the x gather
    for (; e + 1 < end; e += 2) {
        int2 cv0 = g_csr[e];
        int2 cv1 = g_csr[e + 1];
        float x0 = __ldg(&xin[cv0.x * D_IN + lane]);
        float x1 = __ldg(&xin[cv1.x * D_IN + lane]);
        acc = fmaf(__int_as_float(cv0.y), x0, acc);
        acc = fmaf(__int_as_float(cv1.y), x1, acc);
    }
    if (e < end) {
        int2 cv = g_csr[e];
        acc = fmaf(__int_as_float(cv.y), __ldg(&xin[cv.x * D_IN + lane]), acc);
    }

    if (!FUSE) {
        xout[gwarp * D_IN + lane] = acc;
    } else {
        float a0 = bs[lane];
        float a1 = bs[lane + 32];
        #pragma unroll
        for (int d = 0; d < D_IN; ++d) {
            float xv = __shfl_sync(0xffffffffu, acc, d);
            a0 = fmaf(xv, Ws[d * D_OUT + lane], a0);
            a1 = fmaf(xv, Ws[d * D_OUT + lane + 32], a1);
        }
        xout[gwarp * D_OUT + lane]      = a0;
        xout[gwarp * D_OUT + lane + 32] = a1;
    }
}

// ---------------- launch ----------------
extern "C" void kernel_launch(void* const* d_in, const int* in_sizes, int n_in,
                              void* d_out, int out_size) {
    const float* x   = (const float*)d_in[0];
    const int*   er  = (const int*)  d_in[1];
    const int*   ec  = (const int*)  d_in[2];
    const float* ev  = (const float*)d_in[3];
    const float* W   = (const float*)d_in[4];
    const float* b   = (const float*)d_in[5];
    float*       out = (float*)d_out;

    void *p_cnt, *p_pos, *p_rowstart;
    cudaGetSymbolAddress(&p_cnt, g_cnt);
    cudaGetSymbolAddress(&p_pos, g_pos);
    cudaGetSymbolAddress(&p_rowstart, g_rowstart);

    const int EB = 256;
    const int EG = (N_EDGES + EB - 1) / EB;

    // --- CSR build ---
    cudaMemsetAsync(p_cnt, 0, N_NODES * sizeof(int));
    k_hist<<<EG, EB>>>(er);
    k_scan_block<<<N_SCAN_BLK, SCAN_BLK>>>();
    k_scan_sums<<<1, 128>>>();
    k_scan_add<<<N_SCAN_BLK, SCAN_BLK>>>();
    cudaMemcpyAsync(p_pos, p_rowstart, N_NODES * sizeof(int),
                    cudaMemcpyDeviceToDevice);
    k_scatter<<<EG, EB>>>(er, ec, ev);

    // --- 4-hop propagation (k == 4 static), final hop fuses x@W + b ---
    float* buf0;
    float* buf1;
    cudaGetSymbolAddress((void**)&buf0, g_xbuf0);
    cudaGetSymbolAddress((void**)&buf1, g_xbuf1);

    const int SB = 256;                                   // 8 warps per block
    const int SG = (N_NODES + (SB / 32) - 1) / (SB / 32); // 12500 blocks

    k_spmm<false><<<SG, SB>>>(x,    buf0, nullptr, nullptr);
    k_spmm<false><<<SG, SB>>>(buf0, buf1, nullptr, nullptr);
    k_spmm<false><<<SG, SB>>>(buf1, buf0, nullptr, nullptr);
    k_spmm<true ><<<SG, SB>>>(buf0, out,  W, b);
}

// round 2
// speedup vs baseline: 1.1199x; 1.1199x over previous
#include <cuda_runtime.h>
#include <cuda_bf16.h>
#include <cstdint>

#define N_NODES 100000
#define N_EDGES 1600000
#define D_IN    32
#define D_OUT   64

#define SCAN_BLK   1024
#define N_SCAN_BLK ((N_NODES + SCAN_BLK - 1) / SCAN_BLK)   // 98

// ---------------- scratch (static __device__ allocations only) ----------------
__device__ float g_xbuf0[N_NODES * D_IN];
__device__ float g_xbuf1[N_NODES * D_IN];
__device__ int   g_cnt [N_NODES];
__device__ int   g_excl[N_NODES];
__device__ int   g_bsum[128];
__device__ int   g_rowstart[N_NODES + 1];
__device__ int   g_pos[N_NODES];
__device__ int2  g_csr[N_EDGES];          // {col, val bits}

// ---------------- CSR build ----------------
__global__ void k_hist(const int* __restrict__ row) {
    int i = blockIdx.x * blockDim.x + threadIdx.x;   // handles 4 edges
    if (i * 4 < N_EDGES) {
        int4 r = ((const int4*)row)[i];
        atomicAdd(&g_cnt[r.x], 1);
        atomicAdd(&g_cnt[r.y], 1);
        atomicAdd(&g_cnt[r.z], 1);
        atomicAdd(&g_cnt[r.w], 1);
    }
}

__global__ void k_scan_block() {
    __shared__ int s[SCAN_BLK];
    int tid = threadIdx.x;
    int i   = blockIdx.x * SCAN_BLK + tid;
    int v   = (i < N_NODES) ? g_cnt[i] : 0;
    s[tid] = v;
    __syncthreads();
    #pragma unroll
    for (int off = 1; off < SCAN_BLK; off <<= 1) {
        int t = (tid >= off) ? s[tid - off] : 0;
        __syncthreads();
        s[tid] += t;
        __syncthreads();
    }
    int incl = s[tid];
    if (i < N_NODES) g_excl[i] = incl - v;
    if (tid == SCAN_BLK - 1) g_bsum[blockIdx.x] = incl;
}

// fused: scan of block sums (in-smem) + add + write rowstart AND pos
__global__ void k_scan_add() {
    __shared__ int s[128];
    int tid = threadIdx.x;
    if (tid < 128) s[tid] = (tid < N_SCAN_BLK) ? g_bsum[tid] : 0;
    __syncthreads();
    int off = 0;
    for (int j = 0; j < blockIdx.x; ++j) off += s[j];
    int i = blockIdx.x * SCAN_BLK + tid;
    if (i < N_NODES) {
        int v = g_excl[i] + off;
        g_rowstart[i] = v;
        g_pos[i]      = v;
    }
    if (blockIdx.x == 0 && tid == 0) g_rowstart[N_NODES] = N_EDGES;
}

__global__ void k_scatter(const int* __restrict__ row,
                          const int* __restrict__ col,
                          const float* __restrict__ val) {
    int i = blockIdx.x * blockDim.x + threadIdx.x;   // handles 4 edges
    if (i * 4 < N_EDGES) {
        int4   r = ((const int4*)row)[i];
        int4   c = ((const int4*)col)[i];
        float4 v = ((const float4*)val)[i];
        int p;
        p = atomicAdd(&g_pos[r.x], 1); g_csr[p] = make_int2(c.x, __float_as_int(v.x));
        p = atomicAdd(&g_pos[r.y], 1); g_csr[p] = make_int2(c.y, __float_as_int(v.y));
        p = atomicAdd(&g_pos[r.z], 1); g_csr[p] = make_int2(c.z, __float_as_int(v.z));
        p = atomicAdd(&g_pos[r.w], 1); g_csr[p] = make_int2(c.w, __float_as_int(v.w));
    }
}

// ---------------- SpMM: one warp per node, float4 features, 4 edges/iter ----
// lane = grp*8 + sub ; grp in [0,4) picks edge within quad, sub picks float4 chunk
template <bool FUSE>
__global__ __launch_bounds__(256) void k_spmm(const float* __restrict__ xin,
                                              float* __restrict__ xout,
                                              const float* __restrict__ W,
                                              const float* __restrict__ b) {
    __shared__ float Ws[D_IN * D_OUT];   // 8 KB
    __shared__ float bs[D_OUT];
    if (FUSE) {
        for (int i = threadIdx.x; i < D_IN * D_OUT; i += blockDim.x) Ws[i] = W[i];
        if (threadIdx.x < D_OUT) bs[threadIdx.x] = b[threadIdx.x];
        __syncthreads();
    }

    int node = (blockIdx.x * blockDim.x + threadIdx.x) >> 5;
    int lane = threadIdx.x & 31;
    if (node >= N_NODES) return;
    int grp = lane >> 3;      // 0..3 : which edge of the quad
    int sub = lane & 7;       // 0..7 : which float4 of the 32 features

    int start = __ldg(&g_rowstart[node]);
    int end   = __ldg(&g_rowstart[node + 1]);

    float4 acc = make_float4(0.f, 0.f, 0.f, 0.f);
    int e = start;
    // full quads, unrolled x2 for MLP
    for (; e + 8 <= end; e += 8) {
        int2 cv0 = __ldg(&g_csr[e + grp]);
        int2 cv1 = __ldg(&g_csr[e + 4 + grp]);
        float4 x0 = __ldg((const float4*)(xin + (size_t)cv0.x * D_IN) + sub);
        float4 x1 = __ldg((const float4*)(xin + (size_t)cv1.x * D_IN) + sub);
        float v0 = __int_as_float(cv0.y);
        float v1 = __int_as_float(cv1.y);
        acc.x = fmaf(v0, x0.x, acc.x); acc.y = fmaf(v0, x0.y, acc.y);
        acc.z = fmaf(v0, x0.z, acc.z); acc.w = fmaf(v0, x0.w, acc.w);
        acc.x = fmaf(v1, x1.x, acc.x); acc.y = fmaf(v1, x1.y, acc.y);
        acc.z = fmaf(v1, x1.z, acc.z); acc.w = fmaf(v1, x1.w, acc.w);
    }
    for (; e < end; e += 4) {
        int ee = e + grp;
        int2 cv = (ee < end) ? __ldg(&g_csr[ee]) : make_int2(0, 0);
        float4 xv = __ldg((const float4*)(xin + (size_t)cv.x * D_IN) + sub);
        float v = __int_as_float(cv.y);
        acc.x = fmaf(v, xv.x, acc.x); acc.y = fmaf(v, xv.y, acc.y);
        acc.z = fmaf(v, xv.z, acc.z); acc.w = fmaf(v, xv.w, acc.w);
    }

    // reduce the 4 edge-groups: features live at lanes {sub, sub+8, sub+16, sub+24}
    #pragma unroll
    for (int off = 16; off >= 8; off >>= 1) {
        acc.x += __shfl_xor_sync(0xffffffffu, acc.x, off);
        acc.y += __shfl_xor_sync(0xffffffffu, acc.y, off);
        acc.z += __shfl_xor_sync(0xffffffffu, acc.z, off);
        acc.w += __shfl_xor_sync(0xffffffffu, acc.w, off);
    }
    // now every lane holds the full sum for features [4*sub, 4*sub+4)

    if (!FUSE) {
        if (grp == 0)
            ((float4*)(xout + (size_t)node * D_IN))[sub] = acc;
    } else {
        float a0 = bs[lane];
        float a1 = bs[lane + 32];
        #pragma unroll
        for (int d = 0; d < D_IN; ++d) {
            float comp = ((d & 3) == 0) ? acc.x :
                         ((d & 3) == 1) ? acc.y :
                         ((d & 3) == 2) ? acc.z : acc.w;
            float xv = __shfl_sync(0xffffffffu, comp, d >> 2);
            a0 = fmaf(xv, Ws[d * D_OUT + lane], a0);
            a1 = fmaf(xv, Ws[d * D_OUT + lane + 32], a1);
        }
        xout[(size_t)node * D_OUT + lane]      = a0;
        xout[(size_t)node * D_OUT + lane + 32] = a1;
    }
}

// ---------------- launch ----------------
extern "C" void kernel_launch(void* const* d_in, const int* in_sizes, int n_in,
                              void* d_out, int out_size) {
    const float* x   = (const float*)d_in[0];
    const int*   er  = (const int*)  d_in[1];
    const int*   ec  = (const int*)  d_in[2];
    const float* ev  = (const float*)d_in[3];
    const float* W   = (const float*)d_in[4];
    const float* b   = (const float*)d_in[5];
    float*       out = (float*)d_out;

    void* p_cnt;
    cudaGetSymbolAddress(&p_cnt, g_cnt);

    const int EB  = 256;
    const int EG4 = (N_EDGES / 4 + EB - 1) / EB;

    // --- CSR build ---
    cudaMemsetAsync(p_cnt, 0, N_NODES * sizeof(int));
    k_hist<<<EG4, EB>>>(er);
    k_scan_block<<<N_SCAN_BLK, SCAN_BLK>>>();
    k_scan_add<<<N_SCAN_BLK, SCAN_BLK>>>();
    k_scatter<<<EG4, EB>>>(er, ec, ev);

    // --- 4-hop propagation (k == 4 static), final hop fuses x@W + b ---
    float* buf0;
    float* buf1;
    cudaGetSymbolAddress((void**)&buf0, g_xbuf0);
    cudaGetSymbolAddress((void**)&buf1, g_xbuf1);

    const int SB = 256;                                   // 8 warps per block
    const int SG = (N_NODES + (SB / 32) - 1) / (SB / 32); // 12500 blocks

    k_spmm<false><<<SG, SB>>>(x,    buf0, nullptr, nullptr);
    k_spmm<false><<<SG, SB>>>(buf0, buf1, nullptr, nullptr);
    k_spmm<false><<<SG, SB>>>(buf1, buf0, nullptr, nullptr);
    k_spmm<true ><<<SG, SB>>>(buf0, out,  W, b);
}

// round 3
// speedup vs baseline: 1.1495x; 1.0264x over previous
#include <cuda_runtime.h>
#include <cuda_bf16.h>
#include <cstdint>

#define N_NODES 100000
#define N_EDGES 1600000
#define D_IN    32
#define D_OUT   64

#define SCAN_BLK   1024
#define N_SCAN_BLK ((N_NODES + SCAN_BLK - 1) / SCAN_BLK)   // 98

// ---------------- scratch (static __device__ allocations only) ----------------
__device__ float g_xbuf0[N_NODES * D_IN];
__device__ float g_xbuf1[N_NODES * D_IN];
__device__ int   g_cnt [N_NODES];
__device__ int   g_excl[N_NODES];
__device__ int   g_bsum[128];
__device__ int   g_rowstart[N_NODES + 1];
__device__ int   g_pos[N_NODES];
__device__ int2  g_csr[N_EDGES];          // {col, val bits}

// ---------------- CSR build ----------------
__global__ void k_hist(const int* __restrict__ row) {
    int i = blockIdx.x * blockDim.x + threadIdx.x;   // handles 4 edges
    if (i * 4 < N_EDGES) {
        int4 r = ((const int4*)row)[i];
        atomicAdd(&g_cnt[r.x], 1);
        atomicAdd(&g_cnt[r.y], 1);
        atomicAdd(&g_cnt[r.z], 1);
        atomicAdd(&g_cnt[r.w], 1);
    }
}

// warp-shuffle inclusive scan over 1024-thread block
__global__ void k_scan_block() {
    __shared__ int wsum[32];
    int tid  = threadIdx.x;
    int lane = tid & 31;
    int w    = tid >> 5;
    int i    = blockIdx.x * SCAN_BLK + tid;
    int orig = (i < N_NODES) ? g_cnt[i] : 0;
    int v    = orig;
    #pragma unroll
    for (int off = 1; off < 32; off <<= 1) {
        int t = __shfl_up_sync(0xffffffffu, v, off);
        if (lane >= off) v += t;
    }
    if (lane == 31) wsum[w] = v;
    __syncthreads();
    if (w == 0) {
        int s = wsum[lane];
        #pragma unroll
        for (int off = 1; off < 32; off <<= 1) {
            int t = __shfl_up_sync(0xffffffffu, s, off);
            if (lane >= off) s += t;
        }
        wsum[lane] = s;
    }
    __syncthreads();
    int incl = v + ((w > 0) ? wsum[w - 1] : 0);
    if (i < N_NODES) g_excl[i] = incl - orig;
    if (tid == SCAN_BLK - 1) g_bsum[blockIdx.x] = incl;
}

// fused: scan of block sums (in-smem) + add + write rowstart AND pos
__global__ void k_scan_add() {
    __shared__ int s[128];
    int tid = threadIdx.x;
    if (tid < 128) s[tid] = (tid < N_SCAN_BLK) ? g_bsum[tid] : 0;
    __syncthreads();
    int off = 0;
    for (int j = 0; j < blockIdx.x; ++j) off += s[j];
    int i = blockIdx.x * SCAN_BLK + tid;
    if (i < N_NODES) {
        int v = g_excl[i] + off;
        g_rowstart[i] = v;
        g_pos[i]      = v;
    }
    if (blockIdx.x == 0 && tid == 0) g_rowstart[N_NODES] = N_EDGES;
}

// one edge per thread: single atomic->store chain, maximal latency hiding
__global__ void k_scatter(const int* __restrict__ row,
                          const int* __restrict__ col,
                          const float* __restrict__ val) {
    int e = blockIdx.x * blockDim.x + threadIdx.x;
    if (e < N_EDGES) {
        int r = row[e];
        int c = col[e];
        float v = val[e];
        int p = atomicAdd(&g_pos[r], 1);
        g_csr[p] = make_int2(c, __float_as_int(v));
    }
}

// ---------------- SpMM: one warp per node, float4 features, 4 edges/iter ----
// lane = grp*8 + sub ; grp in [0,4) picks edge within quad, sub picks float4 chunk
template <bool FUSE>
__global__ __launch_bounds__(256) void k_spmm(const float* __restrict__ xin,
                                              float* __restrict__ xout,
                                              const float* __restrict__ W,
                                              const float* __restrict__ b) {
    __shared__ float Ws[D_IN * D_OUT];   // 8 KB
    __shared__ float bs[D_OUT];
    if (FUSE) {
        for (int i = threadIdx.x; i < D_IN * D_OUT; i += blockDim.x) Ws[i] = W[i];
        if (threadIdx.x < D_OUT) bs[threadIdx.x] = b[threadIdx.x];
        __syncthreads();
    }

    int node = (blockIdx.x * blockDim.x + threadIdx.x) >> 5;
    int lane = threadIdx.x & 31;
    if (node >= N_NODES) return;
    int grp = lane >> 3;      // 0..3 : which edge of the quad
    int sub = lane & 7;       // 0..7 : which float4 of the 32 features

    int start = __ldg(&g_rowstart[node]);
    int end   = __ldg(&g_rowstart[node + 1]);

    float4 acc = make_float4(0.f, 0.f, 0.f, 0.f);
    int e = start;
    // 16 edges per iter: 4 independent gathers in flight (MLP=4)
    for (; e + 16 <= end; e += 16) {
        int2 cv0 = __ldg(&g_csr[e      + grp]);
        int2 cv1 = __ldg(&g_csr[e + 4  + grp]);
        int2 cv2 = __ldg(&g_csr[e + 8  + grp]);
        int2 cv3 = __ldg(&g_csr[e + 12 + grp]);
        float4 x0 = __ldg((const float4*)(xin + (size_t)cv0.x * D_IN) + sub);
        float4 x1 = __ldg((const float4*)(xin + (size_t)cv1.x * D_IN) + sub);
        float4 x2 = __ldg((const float4*)(xin + (size_t)cv2.x * D_IN) + sub);
        float4 x3 = __ldg((const float4*)(xin + (size_t)cv3.x * D_IN) + sub);
        float v0 = __int_as_float(cv0.y);
        float v1 = __int_as_float(cv1.y);
        float v2 = __int_as_float(cv2.y);
        float v3 = __int_as_float(cv3.y);
        acc.x = fmaf(v0, x0.x, acc.x); acc.y = fmaf(v0, x0.y, acc.y);
        acc.z = fmaf(v0, x0.z, acc.z); acc.w = fmaf(v0, x0.w, acc.w);
        acc.x = fmaf(v1, x1.x, acc.x); acc.y = fmaf(v1, x1.y, acc.y);
        acc.z = fmaf(v1, x1.z, acc.z); acc.w = fmaf(v1, x1.w, acc.w);
        acc.x = fmaf(v2, x2.x, acc.x); acc.y = fmaf(v2, x2.y, acc.y);
        acc.z = fmaf(v2, x2.z, acc.z); acc.w = fmaf(v2, x2.w, acc.w);
        acc.x = fmaf(v3, x3.x, acc.x); acc.y = fmaf(v3, x3.y, acc.y);
        acc.z = fmaf(v3, x3.z, acc.z); acc.w = fmaf(v3, x3.w, acc.w);
    }
    for (; e < end; e += 4) {
        int ee = e + grp;
        int2 cv = (ee < end) ? __ldg(&g_csr[ee]) : make_int2(0, 0);
        float4 xv = __ldg((const float4*)(xin + (size_t)cv.x * D_IN) + sub);
        float v = __int_as_float(cv.y);
        acc.x = fmaf(v, xv.x, acc.x); acc.y = fmaf(v, xv.y, acc.y);
        acc.z = fmaf(v, xv.z, acc.z); acc.w = fmaf(v, xv.w, acc.w);
    }

    // reduce the 4 edge-groups: features live at lanes {sub, sub+8, sub+16, sub+24}
    #pragma unroll
    for (int off = 16; off >= 8; off >>= 1) {
        acc.x += __shfl_xor_sync(0xffffffffu, acc.x, off);
        acc.y += __shfl_xor_sync(0xffffffffu, acc.y, off);
        acc.z += __shfl_xor_sync(0xffffffffu, acc.z, off);
        acc.w += __shfl_xor_sync(0xffffffffu, acc.w, off);
    }
    // now every lane holds the full sum for features [4*sub, 4*sub+4)

    if (!FUSE) {
        if (grp == 0)
            ((float4*)(xout + (size_t)node * D_IN))[sub] = acc;
    } else {
        float a0 = bs[lane];
        float a1 = bs[lane + 32];
        #pragma unroll
        for (int d = 0; d < D_IN; ++d) {
            float comp = ((d & 3) == 0) ? acc.x :
                         ((d & 3) == 1) ? acc.y :
                         ((d & 3) == 2) ? acc.z : acc.w;
            float xv = __shfl_sync(0xffffffffu, comp, d >> 2);
            a0 = fmaf(xv, Ws[d * D_OUT + lane], a0);
            a1 = fmaf(xv, Ws[d * D_OUT + lane + 32], a1);
        }
        xout[(size_t)node * D_OUT + lane]      = a0;
        xout[(size_t)node * D_OUT + lane + 32] = a1;
    }
}

// ---------------- launch ----------------
extern "C" void kernel_launch(void* const* d_in, const int* in_sizes, int n_in,
                              void* d_out, int out_size) {
    const float* x   = (const float*)d_in[0];
    const int*   er  = (const int*)  d_in[1];
    const int*   ec  = (const int*)  d_in[2];
    const float* ev  = (const float*)d_in[3];
    const float* W   = (const float*)d_in[4];
    const float* b   = (const float*)d_in[5];
    float*       out = (float*)d_out;

    void* p_cnt;
    cudaGetSymbolAddress(&p_cnt, g_cnt);

    const int EB  = 256;
    const int EG4 = (N_EDGES / 4 + EB - 1) / EB;
    const int EG1 = (N_EDGES + EB - 1) / EB;

    // --- CSR build ---
    cudaMemsetAsync(p_cnt, 0, N_NODES * sizeof(int));
    k_hist<<<EG4, EB>>>(er);
    k_scan_block<<<N_SCAN_BLK, SCAN_BLK>>>();
    k_scan_add<<<N_SCAN_BLK, SCAN_BLK>>>();
    k_scatter<<<EG1, EB>>>(er, ec, ev);

    // --- 4-hop propagation (k == 4 static), final hop fuses x@W + b ---
    float* buf0;
    float* buf1;
    cudaGetSymbolAddress((void**)&buf0, g_xbuf0);
    cudaGetSymbolAddress((void**)&buf1, g_xbuf1);

    const int SB = 256;                                   // 8 warps per block
    const int SG = (N_NODES + (SB / 32) - 1) / (SB / 32); // 12500 blocks

    k_spmm<false><<<SG, SB>>>(x,    buf0, nullptr, nullptr);
    k_spmm<false><<<SG, SB>>>(buf0, buf1, nullptr, nullptr);
    k_spmm<false><<<SG, SB>>>(buf1, buf0, nullptr, nullptr);
    k_spmm<true ><<<SG, SB>>>(buf0, out,  W, b);
}